// round 9
// baseline (speedup 1.0000x reference)
#include <cuda_runtime.h>
#include <math.h>
#include <stdint.h>

#define NB 32768

// ---------------- scratch (device globals: no allocation allowed) -------------
__device__ float g_q  [NB * 64];        // [B,64]   q = center @ Wq^T
__device__ float g_p  [NB * 512];       // [B,2,256] p[b,h] = q[b,h] @ Wk_h
__device__ float g_wn [NB * 512];       // [B,2,256] attention-weighted neighbor sum
__device__ float g_ctx[NB * 256];       // context

// =============================================================================
// tf32 helpers (legacy mma.sync path — compute_103 baseline, no 'a' features)
// =============================================================================
__device__ __forceinline__ uint32_t f2tf(float x) {
    uint32_t r;
    asm("cvt.rna.tf32.f32 %0, %1;" : "=r"(r) : "f"(x));
    return r;
}

__device__ __forceinline__ float4 f2tf4(float4 v) {
    return make_float4(__uint_as_float(f2tf(v.x)), __uint_as_float(f2tf(v.y)),
                       __uint_as_float(f2tf(v.z)), __uint_as_float(f2tf(v.w)));
}

__device__ __forceinline__ void mma_tf32(float* d, const uint32_t* a, const uint32_t* b) {
    asm volatile(
        "mma.sync.aligned.m16n8k8.row.col.f32.tf32.tf32.f32 "
        "{%0,%1,%2,%3}, {%4,%5,%6,%7}, {%8,%9}, {%0,%1,%2,%3};"
        : "+f"(d[0]), "+f"(d[1]), "+f"(d[2]), "+f"(d[3])
        : "r"(a[0]), "r"(a[1]), "r"(a[2]), "r"(a[3]), "r"(b[0]), "r"(b[1]));
}

// =============================================================================
// GEMM (mma.sync tf32), m-major smem stride 36 (conflict-free; see round 7).
// CTA tile BM=128, BN=64, BK=32; 8 warps 4(m)x2(n); double buffered.
// NCHUNK k-chunks; chunk c reads A_lo if c < 8 else A_hi (virtual concat for
// the fused gate GEMM; A_hi unused when NCHUNK==8).
// EPI=1: out = g*A_lo + (1-g)*A_hi, g = sigmoid(acc + bias)   [gate fusion]
// =============================================================================
#define AS_STR 36
#define AS_FLOATS (128 * AS_STR)     // 4608
#define WS_FLOATS (64 * AS_STR)      // 2304
#define GEMM_SMEM_BYTES ((2 * AS_FLOATS + 2 * WS_FLOATS) * 4)   // 55296

template <int NCHUNK, int EPI>
__device__ __forceinline__ void gemm_body(
    const float* __restrict__ A_lo, const float* __restrict__ A_hi,
    const float* __restrict__ W,
    float* __restrict__ C, int lda, int ldw, int ldc, int m0, int n0,
    const float* __restrict__ bias, float* __restrict__ outp, float* ds)
{
    float* Asb[2] = {ds, ds + AS_FLOATS};
    float* Wsb[2] = {ds + 2 * AS_FLOATS, ds + 2 * AS_FLOATS + WS_FLOATS};

    const int tid  = threadIdx.x;
    const int wid  = tid >> 5;
    const int lane = tid & 31;
    const int wm   = (wid & 3) * 32;
    const int wn   = (wid >> 2) * 32;

    float4 ra[4], rw[2];
    {
        const float* Ab = A_lo + (size_t)m0 * lda;
        const float* Wb = W + (size_t)n0 * ldw;
#pragma unroll
        for (int i = 0; i < 4; i++) {
            const int idx = tid + 256 * i, r = idx >> 3, kq = idx & 7;
            ra[i] = *(const float4*)(Ab + (size_t)r * lda + kq * 4);
        }
#pragma unroll
        for (int i = 0; i < 2; i++) {
            const int idx = tid + 256 * i, r = idx >> 3, kq = idx & 7;
            rw[i] = *(const float4*)(Wb + (size_t)r * ldw + kq * 4);
        }
    }

    float acc[2][4][4];
#pragma unroll
    for (int i = 0; i < 2; i++)
#pragma unroll
        for (int j = 0; j < 4; j++)
#pragma unroll
            for (int v = 0; v < 4; v++) acc[i][j][v] = 0.f;

    {   // stage chunk 0
        float* As = Asb[0];
        float* Ws = Wsb[0];
#pragma unroll
        for (int i = 0; i < 4; i++) {
            const int idx = tid + 256 * i, r = idx >> 3, kq = idx & 7;
            *(float4*)&As[r * AS_STR + kq * 4] = f2tf4(ra[i]);
        }
#pragma unroll
        for (int i = 0; i < 2; i++) {
            const int idx = tid + 256 * i, r = idx >> 3, kq = idx & 7;
            *(float4*)&Ws[r * AS_STR + kq * 4] = f2tf4(rw[i]);
        }
    }
    __syncthreads();

#pragma unroll 1
    for (int it = 0; it < NCHUNK; it++) {
        const int cur = it & 1;
        if (it < NCHUNK - 1) {
            const int nc = it + 1;
            const float* Abase = (NCHUNK == 8 || nc < 8) ? A_lo : A_hi;
            const int ka = (NCHUNK == 8 || nc < 8) ? nc * 32 : (nc - 8) * 32;
            const float* Ab = Abase + (size_t)m0 * lda + ka;
            const float* Wb = W + (size_t)n0 * ldw + nc * 32;
#pragma unroll
            for (int i = 0; i < 4; i++) {
                const int idx = tid + 256 * i, r = idx >> 3, kq = idx & 7;
                ra[i] = *(const float4*)(Ab + (size_t)r * lda + kq * 4);
            }
#pragma unroll
            for (int i = 0; i < 2; i++) {
                const int idx = tid + 256 * i, r = idx >> 3, kq = idx & 7;
                rw[i] = *(const float4*)(Wb + (size_t)r * ldw + kq * 4);
            }
        }
        {
            const float* As = Asb[cur];
            const float* Ws = Wsb[cur];
            const int c = lane & 3, r = lane >> 2;
#pragma unroll
            for (int ks = 0; ks < 4; ks++) {
                const int kk = ks * 8;
                uint32_t afr[2][4], bfr[4][2];
#pragma unroll
                for (int i = 0; i < 2; i++) {
                    const int r0 = wm + i * 16 + r;
                    afr[i][0] = __float_as_uint(As[r0 * AS_STR + kk + c]);
                    afr[i][1] = __float_as_uint(As[(r0 + 8) * AS_STR + kk + c]);
                    afr[i][2] = __float_as_uint(As[r0 * AS_STR + kk + c + 4]);
                    afr[i][3] = __float_as_uint(As[(r0 + 8) * AS_STR + kk + c + 4]);
                }
#pragma unroll
                for (int j = 0; j < 4; j++) {
                    const int c0 = wn + j * 8 + r;
                    bfr[j][0] = __float_as_uint(Ws[c0 * AS_STR + kk + c]);
                    bfr[j][1] = __float_as_uint(Ws[c0 * AS_STR + kk + c + 4]);
                }
#pragma unroll
                for (int i = 0; i < 2; i++)
#pragma unroll
                    for (int j = 0; j < 4; j++)
                        mma_tf32(acc[i][j], afr[i], bfr[j]);
            }
        }
        if (it < NCHUNK - 1) {
            const int nxt = 1 - cur;
            float* As = Asb[nxt];
            float* Ws = Wsb[nxt];
#pragma unroll
            for (int i = 0; i < 4; i++) {
                const int idx = tid + 256 * i, r = idx >> 3, kq = idx & 7;
                *(float4*)&As[r * AS_STR + kq * 4] = f2tf4(ra[i]);
            }
#pragma unroll
            for (int i = 0; i < 2; i++) {
                const int idx = tid + 256 * i, r = idx >> 3, kq = idx & 7;
                *(float4*)&Ws[r * AS_STR + kq * 4] = f2tf4(rw[i]);
            }
        }
        __syncthreads();
    }

    const int r = lane >> 2, c2 = (lane & 3) * 2;
#pragma unroll
    for (int i = 0; i < 2; i++) {
#pragma unroll
        for (int j = 0; j < 4; j++) {
            const int row0 = m0 + wm + i * 16 + r;
            const int col  = n0 + wn + j * 8 + c2;
#pragma unroll
            for (int half = 0; half < 2; half++) {
                const int row = row0 + half * 8;
                const float d0 = acc[i][j][2 * half + 0];
                const float d1 = acc[i][j][2 * half + 1];
                if (EPI == 0) {
                    *(float2*)(C + (size_t)row * ldc + col) = make_float2(d0, d1);
                } else {
                    const float2 bv = *(const float2*)(bias + col);
                    const float2 cv = *(const float2*)(A_lo + (size_t)row * lda + col);
                    const float2 xv = *(const float2*)(A_hi + (size_t)row * lda + col);
                    const float gg0 = 1.f / (1.f + __expf(-(d0 + bv.x)));
                    const float gg1 = 1.f / (1.f + __expf(-(d1 + bv.y)));
                    float2 o;
                    o.x = gg0 * cv.x + (1.f - gg0) * xv.x;
                    o.y = gg1 * cv.y + (1.f - gg1) * xv.y;
                    *(float2*)(outp + (size_t)row * 256 + col) = o;
                }
            }
        }
    }
}

// Dual-problem GEMM (K=256): blockIdx.y < ysplit -> problem 1, else problem 2.
__global__ __launch_bounds__(256) void gemm_dual(
    const float* __restrict__ A1, const float* __restrict__ W1, float* __restrict__ C1,
    int lda1, int ldw1, int ldc1,
    const float* __restrict__ A2, const float* __restrict__ W2, float* __restrict__ C2,
    int lda2, int ldw2, int ldc2, int ysplit)
{
    extern __shared__ float ds[];
    const int y  = blockIdx.y;
    const int m0 = blockIdx.x * 128;
    if (y < ysplit)
        gemm_body<8, 0>(A1, A1, W1, C1, lda1, ldw1, ldc1, m0, y * 64,
                        nullptr, nullptr, ds);
    else
        gemm_body<8, 0>(A2, A2, W2, C2, lda2, ldw2, ldc2, m0, (y - ysplit) * 64,
                        nullptr, nullptr, ds);
}

// Fused gate GEMM: K=512 over virtual concat(center, ctx); epilogue =
// sigmoid(acc + bias) blend of center/ctx. g1 buffer eliminated entirely.
__global__ __launch_bounds__(256) void gemm_gate(
    const float* __restrict__ center, const float* __restrict__ ctx,
    const float* __restrict__ Wg, const float* __restrict__ bias,
    float* __restrict__ outp)
{
    extern __shared__ float ds[];
    gemm_body<16, 1>(center, ctx, Wg, nullptr, 256, 512, 0,
                     blockIdx.x * 128, blockIdx.y * 64, bias, outp, ds);
}

// =============================================================================
// p kernel:  p[b,h,d] = sum_{a<32} q[b, h*32+a] * Wk[h*32+a, d]
// =============================================================================
__global__ __launch_bounds__(256) void p_kernel(const float* __restrict__ Wk)
{
    __shared__ float qs[16 * 64];
    const int t = threadIdx.x;              // t == d
    float wk[64];
#pragma unroll
    for (int r = 0; r < 64; r++) wk[r] = Wk[r * 256 + t];

    const int b0 = blockIdx.x * 16;
    const float4* qsrc = (const float4*)(g_q + (size_t)b0 * 64);
    ((float4*)qs)[t] = qsrc[t];
    __syncthreads();

#pragma unroll 1
    for (int bb = 0; bb < 16; bb++) {
        float p0 = 0.f, p1 = 0.f;
#pragma unroll
        for (int a4 = 0; a4 < 8; a4++) {
            const float4 q0 = *(const float4*)&qs[bb * 64 + a4 * 4];
            const float4 q1 = *(const float4*)&qs[bb * 64 + 32 + a4 * 4];
            p0 = fmaf(q0.x, wk[a4 * 4 + 0], p0);
            p0 = fmaf(q0.y, wk[a4 * 4 + 1], p0);
            p0 = fmaf(q0.z, wk[a4 * 4 + 2], p0);
            p0 = fmaf(q0.w, wk[a4 * 4 + 3], p0);
            p1 = fmaf(q1.x, wk[32 + a4 * 4 + 0], p1);
            p1 = fmaf(q1.y, wk[32 + a4 * 4 + 1], p1);
            p1 = fmaf(q1.z, wk[32 + a4 * 4 + 2], p1);
            p1 = fmaf(q1.w, wk[32 + a4 * 4 + 3], p1);
        }
        const size_t o = (size_t)(b0 + bb) * 512;
        g_p[o + t]       = p0;
        g_p[o + 256 + t] = p1;
    }
}

// =============================================================================
// Register-resident attention, occupancy-tuned: one CTA per b, 256 threads.
// Same structure as the proven round-4 kernel, but p staged through smem
// (rematerializable LDS instead of 16 pinned regs) and __launch_bounds__
// min-blocks=3 -> <=85 regs -> 3 CTAs/SM (24 warps) for deeper DRAM overlap.
// =============================================================================
__global__ __launch_bounds__(256, 3) void attn_reg(
    const float* __restrict__ neigh, const float* __restrict__ wts)
{
    __shared__ float sAcc[8][512];        // 16 KB cross-warp reduction
    __shared__ float sScore[2][64];
    __shared__ float sAttn[2][64];
    __shared__ float sWt[64];
    __shared__ float sP[512];

    const int b    = blockIdx.x;
    const int t    = threadIdx.x;
    const int w    = t >> 5;
    const int lane = t & 31;

    const float* nbp = neigh + (size_t)b * 64 * 256;

    float4 va[8], vb[8];
#pragma unroll
    for (int it = 0; it < 8; it++) {            // front-batched: 16 LDG.128
        const int k = it * 8 + w;
        va[it] = *(const float4*)(nbp + k * 256 + 4 * lane);
        vb[it] = *(const float4*)(nbp + k * 256 + 128 + 4 * lane);
    }

    if (t < 128) ((float4*)sP)[t] = ((const float4*)(g_p + (size_t)b * 512))[t];
    if (t >= 128 && t < 192)
        sWt[t - 128] = wts[(size_t)b * 64 + (t - 128)] * 0.17677669529663687f;
    __syncthreads();

#pragma unroll
    for (int it = 0; it < 8; it++) {
        const float4 p0a = ((const float4*)sP)[lane];
        const float4 p0b = ((const float4*)sP)[32 + lane];
        const float4 p1a = ((const float4*)sP)[64 + lane];
        const float4 p1b = ((const float4*)sP)[96 + lane];
        float s0 = va[it].x * p0a.x + va[it].y * p0a.y + va[it].z * p0a.z + va[it].w * p0a.w
                 + vb[it].x * p0b.x + vb[it].y * p0b.y + vb[it].z * p0b.z + vb[it].w * p0b.w;
        float s1 = va[it].x * p1a.x + va[it].y * p1a.y + va[it].z * p1a.z + va[it].w * p1a.w
                 + vb[it].x * p1b.x + vb[it].y * p1b.y + vb[it].z * p1b.z + vb[it].w * p1b.w;
#pragma unroll
        for (int o = 16; o; o >>= 1) {
            s0 += __shfl_xor_sync(0xffffffffu, s0, o);
            s1 += __shfl_xor_sync(0xffffffffu, s1, o);
        }
        if (lane == 0) {
            sScore[0][it * 8 + w] = s0;
            sScore[1][it * 8 + w] = s1;
        }
    }
    __syncthreads();

    if (t < 64) {                    // warps 0,1: one head each
        const int h = t >> 5, l = t & 31;
        const float sa = sScore[h][l]      * sWt[l];
        const float sb = sScore[h][32 + l] * sWt[32 + l];
        float mx = fmaxf(sa, sb);
#pragma unroll
        for (int o = 16; o; o >>= 1) mx = fmaxf(mx, __shfl_xor_sync(0xffffffffu, mx, o));
        const float ea = __expf(sa - mx), eb = __expf(sb - mx);
        float sum = ea + eb;
#pragma unroll
        for (int o = 16; o; o >>= 1) sum += __shfl_xor_sync(0xffffffffu, sum, o);
        const float inv = 1.f / sum;
        sAttn[h][l]      = ea * inv;
        sAttn[h][32 + l] = eb * inv;
    }
    __syncthreads();

    float4 a0a = {0,0,0,0}, a0b = {0,0,0,0}, a1a = {0,0,0,0}, a1b = {0,0,0,0};
#pragma unroll
    for (int it = 0; it < 8; it++) {
        const float w0 = sAttn[0][it * 8 + w];   // warp-uniform broadcast
        const float w1 = sAttn[1][it * 8 + w];
        a0a.x = fmaf(w0, va[it].x, a0a.x);  a0a.y = fmaf(w0, va[it].y, a0a.y);
        a0a.z = fmaf(w0, va[it].z, a0a.z);  a0a.w = fmaf(w0, va[it].w, a0a.w);
        a0b.x = fmaf(w0, vb[it].x, a0b.x);  a0b.y = fmaf(w0, vb[it].y, a0b.y);
        a0b.z = fmaf(w0, vb[it].z, a0b.z);  a0b.w = fmaf(w0, vb[it].w, a0b.w);
        a1a.x = fmaf(w1, va[it].x, a1a.x);  a1a.y = fmaf(w1, va[it].y, a1a.y);
        a1a.z = fmaf(w1, va[it].z, a1a.z);  a1a.w = fmaf(w1, va[it].w, a1a.w);
        a1b.x = fmaf(w1, vb[it].x, a1b.x);  a1b.y = fmaf(w1, vb[it].y, a1b.y);
        a1b.z = fmaf(w1, vb[it].z, a1b.z);  a1b.w = fmaf(w1, vb[it].w, a1b.w);
    }

    float4* row = (float4*)&sAcc[w][0];
    row[lane]      = a0a;
    row[32 + lane] = a0b;
    row[64 + lane] = a1a;
    row[96 + lane] = a1b;
    __syncthreads();

    float s_lo = 0.f, s_hi = 0.f;
#pragma unroll
    for (int ww = 0; ww < 8; ww++) {
        s_lo += sAcc[ww][t];
        s_hi += sAcc[ww][t + 256];
    }
    g_wn[(size_t)b * 512 + t]       = s_lo;
    g_wn[(size_t)b * 512 + 256 + t] = s_hi;
}

// =============================================================================
extern "C" void kernel_launch(void* const* d_in, const int* in_sizes, int n_in,
                              void* d_out, int out_size)
{
    const float* center = (const float*)d_in[0];
    const float* neigh  = (const float*)d_in[1];
    const float* wts    = (const float*)d_in[2];
    const float* Wq     = (const float*)d_in[3];
    const float* Wk     = (const float*)d_in[4];
    const float* Wv     = (const float*)d_in[5];
    const float* Wg     = (const float*)d_in[6];
    const float* bg     = (const float*)d_in[7];
    float* out = (float*)d_out;

    float *q_, *wn_, *ctx_;
    cudaGetSymbolAddress((void**)&q_,   g_q);
    cudaGetSymbolAddress((void**)&wn_,  g_wn);
    cudaGetSymbolAddress((void**)&ctx_, g_ctx);

    cudaFuncSetAttribute(gemm_dual,
                         cudaFuncAttributeMaxDynamicSharedMemorySize, GEMM_SMEM_BYTES);
    cudaFuncSetAttribute(gemm_gate,
                         cudaFuncAttributeMaxDynamicSharedMemorySize, GEMM_SMEM_BYTES);

    const dim3 blk(256);

    // q = center @ Wq^T                       [B,64]
    gemm_dual<<<dim3(256, 1), blk, GEMM_SMEM_BYTES>>>(
        center, Wq, q_, 256, 256, 64,
        center, Wq, q_, 256, 256, 64, 1);
    // p[b,h] = q[b,h] @ Wk_h                  [B,2,256]
    p_kernel<<<2048, blk>>>(Wk);
    // attention -> wn                         [B,2,256]
    attn_reg<<<NB, blk>>>(neigh, wts);
    // context_h = wn_h @ Wv_h^T               [B,256] (both heads, one launch)
    gemm_dual<<<dim3(256, 4), blk, GEMM_SMEM_BYTES>>>(
        wn_,       Wv,             ctx_,       512, 256, 256,
        wn_ + 256, Wv + 128 * 256, ctx_ + 128, 512, 256, 256, 2);
    // gate = sigmoid(concat(center,ctx) @ Wg^T + bg); out = gate*center+(1-gate)*ctx
    gemm_gate<<<dim3(256, 4), blk, GEMM_SMEM_BYTES>>>(
        center, ctx_, Wg, bg, out);
}

// round 10
// speedup vs baseline: 1.0894x; 1.0894x over previous
#include <cuda_runtime.h>
#include <math.h>
#include <stdint.h>

#define NB 32768

// ---------------- scratch (device globals: no allocation allowed) -------------
__device__ float g_q  [NB * 64];        // [B,64]   q = center @ Wq^T
__device__ float g_p  [NB * 512];       // [B,2,256] p[b,h] = q[b,h] @ Wk_h
__device__ float g_wn [NB * 512];       // [B,2,256] attention-weighted neighbor sum
__device__ float g_ctx[NB * 256];       // context

// =============================================================================
// tf32 helpers (legacy mma.sync path — compute_103 baseline, no 'a' features)
// =============================================================================
__device__ __forceinline__ uint32_t f2tf(float x) {
    uint32_t r;
    asm("cvt.rna.tf32.f32 %0, %1;" : "=r"(r) : "f"(x));
    return r;
}

__device__ __forceinline__ float4 f2tf4(float4 v) {
    return make_float4(__uint_as_float(f2tf(v.x)), __uint_as_float(f2tf(v.y)),
                       __uint_as_float(f2tf(v.z)), __uint_as_float(f2tf(v.w)));
}

__device__ __forceinline__ void mma_tf32(float* d, const uint32_t* a, const uint32_t* b) {
    asm volatile(
        "mma.sync.aligned.m16n8k8.row.col.f32.tf32.tf32.f32 "
        "{%0,%1,%2,%3}, {%4,%5,%6,%7}, {%8,%9}, {%0,%1,%2,%3};"
        : "+f"(d[0]), "+f"(d[1]), "+f"(d[2]), "+f"(d[3])
        : "r"(a[0]), "r"(a[1]), "r"(a[2]), "r"(a[3]), "r"(b[0]), "r"(b[1]));
}

// =============================================================================
// GEMM (mma.sync tf32), m-major smem stride 36 (conflict-free; round 7).
// CTA tile BM=128, BN=64, BK=32; 8 warps 4(m)x2(n); double buffered.
// NCHUNK k-chunks; chunk c reads A_lo if c < 8 else A_hi (virtual concat for
// the fused gate GEMM; A_hi unused when NCHUNK==8).
// EPI=1: out = g*A_lo + (1-g)*A_hi, g = sigmoid(acc + bias)   [gate fusion]
// =============================================================================
#define AS_STR 36
#define AS_FLOATS (128 * AS_STR)     // 4608
#define WS_FLOATS (64 * AS_STR)      // 2304
#define GEMM_SMEM_BYTES ((2 * AS_FLOATS + 2 * WS_FLOATS) * 4)   // 55296

template <int NCHUNK, int EPI>
__device__ __forceinline__ void gemm_body(
    const float* __restrict__ A_lo, const float* __restrict__ A_hi,
    const float* __restrict__ W,
    float* __restrict__ C, int lda, int ldw, int ldc, int m0, int n0,
    const float* __restrict__ bias, float* __restrict__ outp, float* ds)
{
    float* Asb[2] = {ds, ds + AS_FLOATS};
    float* Wsb[2] = {ds + 2 * AS_FLOATS, ds + 2 * AS_FLOATS + WS_FLOATS};

    const int tid  = threadIdx.x;
    const int wid  = tid >> 5;
    const int lane = tid & 31;
    const int wm   = (wid & 3) * 32;
    const int wn   = (wid >> 2) * 32;

    float4 ra[4], rw[2];
    {
        const float* Ab = A_lo + (size_t)m0 * lda;
        const float* Wb = W + (size_t)n0 * ldw;
#pragma unroll
        for (int i = 0; i < 4; i++) {
            const int idx = tid + 256 * i, r = idx >> 3, kq = idx & 7;
            ra[i] = *(const float4*)(Ab + (size_t)r * lda + kq * 4);
        }
#pragma unroll
        for (int i = 0; i < 2; i++) {
            const int idx = tid + 256 * i, r = idx >> 3, kq = idx & 7;
            rw[i] = *(const float4*)(Wb + (size_t)r * ldw + kq * 4);
        }
    }

    float acc[2][4][4];
#pragma unroll
    for (int i = 0; i < 2; i++)
#pragma unroll
        for (int j = 0; j < 4; j++)
#pragma unroll
            for (int v = 0; v < 4; v++) acc[i][j][v] = 0.f;

    {   // stage chunk 0
        float* As = Asb[0];
        float* Ws = Wsb[0];
#pragma unroll
        for (int i = 0; i < 4; i++) {
            const int idx = tid + 256 * i, r = idx >> 3, kq = idx & 7;
            *(float4*)&As[r * AS_STR + kq * 4] = f2tf4(ra[i]);
        }
#pragma unroll
        for (int i = 0; i < 2; i++) {
            const int idx = tid + 256 * i, r = idx >> 3, kq = idx & 7;
            *(float4*)&Ws[r * AS_STR + kq * 4] = f2tf4(rw[i]);
        }
    }
    __syncthreads();

#pragma unroll 1
    for (int it = 0; it < NCHUNK; it++) {
        const int cur = it & 1;
        if (it < NCHUNK - 1) {
            const int nc = it + 1;
            const float* Abase = (NCHUNK == 8 || nc < 8) ? A_lo : A_hi;
            const int ka = (NCHUNK == 8 || nc < 8) ? nc * 32 : (nc - 8) * 32;
            const float* Ab = Abase + (size_t)m0 * lda + ka;
            const float* Wb = W + (size_t)n0 * ldw + nc * 32;
#pragma unroll
            for (int i = 0; i < 4; i++) {
                const int idx = tid + 256 * i, r = idx >> 3, kq = idx & 7;
                ra[i] = *(const float4*)(Ab + (size_t)r * lda + kq * 4);
            }
#pragma unroll
            for (int i = 0; i < 2; i++) {
                const int idx = tid + 256 * i, r = idx >> 3, kq = idx & 7;
                rw[i] = *(const float4*)(Wb + (size_t)r * ldw + kq * 4);
            }
        }
        {
            const float* As = Asb[cur];
            const float* Ws = Wsb[cur];
            const int c = lane & 3, r = lane >> 2;
#pragma unroll
            for (int ks = 0; ks < 4; ks++) {
                const int kk = ks * 8;
                uint32_t afr[2][4], bfr[4][2];
#pragma unroll
                for (int i = 0; i < 2; i++) {
                    const int r0 = wm + i * 16 + r;
                    afr[i][0] = __float_as_uint(As[r0 * AS_STR + kk + c]);
                    afr[i][1] = __float_as_uint(As[(r0 + 8) * AS_STR + kk + c]);
                    afr[i][2] = __float_as_uint(As[r0 * AS_STR + kk + c + 4]);
                    afr[i][3] = __float_as_uint(As[(r0 + 8) * AS_STR + kk + c + 4]);
                }
#pragma unroll
                for (int j = 0; j < 4; j++) {
                    const int c0 = wn + j * 8 + r;
                    bfr[j][0] = __float_as_uint(Ws[c0 * AS_STR + kk + c]);
                    bfr[j][1] = __float_as_uint(Ws[c0 * AS_STR + kk + c + 4]);
                }
#pragma unroll
                for (int i = 0; i < 2; i++)
#pragma unroll
                    for (int j = 0; j < 4; j++)
                        mma_tf32(acc[i][j], afr[i], bfr[j]);
            }
        }
        if (it < NCHUNK - 1) {
            const int nxt = 1 - cur;
            float* As = Asb[nxt];
            float* Ws = Wsb[nxt];
#pragma unroll
            for (int i = 0; i < 4; i++) {
                const int idx = tid + 256 * i, r = idx >> 3, kq = idx & 7;
                *(float4*)&As[r * AS_STR + kq * 4] = f2tf4(ra[i]);
            }
#pragma unroll
            for (int i = 0; i < 2; i++) {
                const int idx = tid + 256 * i, r = idx >> 3, kq = idx & 7;
                *(float4*)&Ws[r * AS_STR + kq * 4] = f2tf4(rw[i]);
            }
        }
        __syncthreads();
    }

    const int r = lane >> 2, c2 = (lane & 3) * 2;
#pragma unroll
    for (int i = 0; i < 2; i++) {
#pragma unroll
        for (int j = 0; j < 4; j++) {
            const int row0 = m0 + wm + i * 16 + r;
            const int col  = n0 + wn + j * 8 + c2;
#pragma unroll
            for (int half = 0; half < 2; half++) {
                const int row = row0 + half * 8;
                const float d0 = acc[i][j][2 * half + 0];
                const float d1 = acc[i][j][2 * half + 1];
                if (EPI == 0) {
                    *(float2*)(C + (size_t)row * ldc + col) = make_float2(d0, d1);
                } else {
                    const float2 bv = *(const float2*)(bias + col);
                    const float2 cv = *(const float2*)(A_lo + (size_t)row * lda + col);
                    const float2 xv = *(const float2*)(A_hi + (size_t)row * lda + col);
                    const float gg0 = 1.f / (1.f + __expf(-(d0 + bv.x)));
                    const float gg1 = 1.f / (1.f + __expf(-(d1 + bv.y)));
                    float2 o;
                    o.x = gg0 * cv.x + (1.f - gg0) * xv.x;
                    o.y = gg1 * cv.y + (1.f - gg1) * xv.y;
                    *(float2*)(outp + (size_t)row * 256 + col) = o;
                }
            }
        }
    }
}

// Dual-problem GEMM (K=256): blockIdx.y < ysplit -> problem 1, else problem 2.
__global__ __launch_bounds__(256) void gemm_dual(
    const float* __restrict__ A1, const float* __restrict__ W1, float* __restrict__ C1,
    int lda1, int ldw1, int ldc1,
    const float* __restrict__ A2, const float* __restrict__ W2, float* __restrict__ C2,
    int lda2, int ldw2, int ldc2, int ysplit)
{
    extern __shared__ float ds[];
    const int y  = blockIdx.y;
    const int m0 = blockIdx.x * 128;
    if (y < ysplit)
        gemm_body<8, 0>(A1, A1, W1, C1, lda1, ldw1, ldc1, m0, y * 64,
                        nullptr, nullptr, ds);
    else
        gemm_body<8, 0>(A2, A2, W2, C2, lda2, ldw2, ldc2, m0, (y - ysplit) * 64,
                        nullptr, nullptr, ds);
}

// Fused gate GEMM: K=512 over virtual concat(center, ctx); epilogue =
// sigmoid(acc + bias) blend of center/ctx. g1 buffer eliminated entirely.
__global__ __launch_bounds__(256) void gemm_gate(
    const float* __restrict__ center, const float* __restrict__ ctx,
    const float* __restrict__ Wg, const float* __restrict__ bias,
    float* __restrict__ outp)
{
    extern __shared__ float ds[];
    gemm_body<16, 1>(center, ctx, Wg, nullptr, 256, 512, 0,
                     blockIdx.x * 128, blockIdx.y * 64, bias, outp, ds);
}

// =============================================================================
// p kernel:  p[b,h,d] = sum_{a<32} q[b, h*32+a] * Wk[h*32+a, d]
// =============================================================================
__global__ __launch_bounds__(256) void p_kernel(const float* __restrict__ Wk)
{
    __shared__ float qs[16 * 64];
    const int t = threadIdx.x;              // t == d
    float wk[64];
#pragma unroll
    for (int r = 0; r < 64; r++) wk[r] = Wk[r * 256 + t];

    const int b0 = blockIdx.x * 16;
    const float4* qsrc = (const float4*)(g_q + (size_t)b0 * 64);
    ((float4*)qs)[t] = qsrc[t];
    __syncthreads();

#pragma unroll 1
    for (int bb = 0; bb < 16; bb++) {
        float p0 = 0.f, p1 = 0.f;
#pragma unroll
        for (int a4 = 0; a4 < 8; a4++) {
            const float4 q0 = *(const float4*)&qs[bb * 64 + a4 * 4];
            const float4 q1 = *(const float4*)&qs[bb * 64 + 32 + a4 * 4];
            p0 = fmaf(q0.x, wk[a4 * 4 + 0], p0);
            p0 = fmaf(q0.y, wk[a4 * 4 + 1], p0);
            p0 = fmaf(q0.z, wk[a4 * 4 + 2], p0);
            p0 = fmaf(q0.w, wk[a4 * 4 + 3], p0);
            p1 = fmaf(q1.x, wk[32 + a4 * 4 + 0], p1);
            p1 = fmaf(q1.y, wk[32 + a4 * 4 + 1], p1);
            p1 = fmaf(q1.z, wk[32 + a4 * 4 + 2], p1);
            p1 = fmaf(q1.w, wk[32 + a4 * 4 + 3], p1);
        }
        const size_t o = (size_t)(b0 + bb) * 512;
        g_p[o + t]       = p0;
        g_p[o + 256 + t] = p1;
    }
}

// =============================================================================
// Register-resident attention (EXACT round-4/6 proven version — no launch
// bound, p in registers, regs=104, 2 CTAs/SM, 366us @ DRAM 79%).
// =============================================================================
__global__ __launch_bounds__(256) void attn_reg(
    const float* __restrict__ neigh, const float* __restrict__ wts)
{
    __shared__ float sAcc[8][512];        // 16 KB cross-warp reduction
    __shared__ float sScore[2][64];
    __shared__ float sAttn[2][64];
    __shared__ float sWt[64];

    const int b    = blockIdx.x;
    const int t    = threadIdx.x;
    const int w    = t >> 5;
    const int lane = t & 31;

    if (t < 64) sWt[t] = wts[(size_t)b * 64 + t] * 0.17677669529663687f; // /sqrt(32)

    const float4* pp = (const float4*)(g_p + (size_t)b * 512);
    const float4 p0a = pp[lane];
    const float4 p0b = pp[32 + lane];
    const float4 p1a = pp[64 + lane];
    const float4 p1b = pp[96 + lane];

    const float* nbp = neigh + (size_t)b * 64 * 256;

    float4 va[8], vb[8];
#pragma unroll
    for (int it = 0; it < 8; it++) {            // front-batched: 16 LDG.128
        const int k = it * 8 + w;
        va[it] = *(const float4*)(nbp + k * 256 + 4 * lane);
        vb[it] = *(const float4*)(nbp + k * 256 + 128 + 4 * lane);
    }

#pragma unroll
    for (int it = 0; it < 8; it++) {
        float s0 = va[it].x * p0a.x + va[it].y * p0a.y + va[it].z * p0a.z + va[it].w * p0a.w
                 + vb[it].x * p0b.x + vb[it].y * p0b.y + vb[it].z * p0b.z + vb[it].w * p0b.w;
        float s1 = va[it].x * p1a.x + va[it].y * p1a.y + va[it].z * p1a.z + va[it].w * p1a.w
                 + vb[it].x * p1b.x + vb[it].y * p1b.y + vb[it].z * p1b.z + vb[it].w * p1b.w;
#pragma unroll
        for (int o = 16; o; o >>= 1) {
            s0 += __shfl_xor_sync(0xffffffffu, s0, o);
            s1 += __shfl_xor_sync(0xffffffffu, s1, o);
        }
        if (lane == 0) {
            sScore[0][it * 8 + w] = s0;
            sScore[1][it * 8 + w] = s1;
        }
    }
    __syncthreads();

    if (t < 64) {                    // warps 0,1: one head each
        const int h = t >> 5, l = t & 31;
        const float sa = sScore[h][l]      * sWt[l];
        const float sb = sScore[h][32 + l] * sWt[32 + l];
        float mx = fmaxf(sa, sb);
#pragma unroll
        for (int o = 16; o; o >>= 1) mx = fmaxf(mx, __shfl_xor_sync(0xffffffffu, mx, o));
        const float ea = __expf(sa - mx), eb = __expf(sb - mx);
        float sum = ea + eb;
#pragma unroll
        for (int o = 16; o; o >>= 1) sum += __shfl_xor_sync(0xffffffffu, sum, o);
        const float inv = 1.f / sum;
        sAttn[h][l]      = ea * inv;
        sAttn[h][32 + l] = eb * inv;
    }
    __syncthreads();

    float4 a0a = {0,0,0,0}, a0b = {0,0,0,0}, a1a = {0,0,0,0}, a1b = {0,0,0,0};
#pragma unroll
    for (int it = 0; it < 8; it++) {
        const float w0 = sAttn[0][it * 8 + w];   // warp-uniform broadcast
        const float w1 = sAttn[1][it * 8 + w];
        a0a.x = fmaf(w0, va[it].x, a0a.x);  a0a.y = fmaf(w0, va[it].y, a0a.y);
        a0a.z = fmaf(w0, va[it].z, a0a.z);  a0a.w = fmaf(w0, va[it].w, a0a.w);
        a0b.x = fmaf(w0, vb[it].x, a0b.x);  a0b.y = fmaf(w0, vb[it].y, a0b.y);
        a0b.z = fmaf(w0, vb[it].z, a0b.z);  a0b.w = fmaf(w0, vb[it].w, a0b.w);
        a1a.x = fmaf(w1, va[it].x, a1a.x);  a1a.y = fmaf(w1, va[it].y, a1a.y);
        a1a.z = fmaf(w1, va[it].z, a1a.z);  a1a.w = fmaf(w1, va[it].w, a1a.w);
        a1b.x = fmaf(w1, vb[it].x, a1b.x);  a1b.y = fmaf(w1, vb[it].y, a1b.y);
        a1b.z = fmaf(w1, vb[it].z, a1b.z);  a1b.w = fmaf(w1, vb[it].w, a1b.w);
    }

    float4* row = (float4*)&sAcc[w][0];
    row[lane]      = a0a;
    row[32 + lane] = a0b;
    row[64 + lane] = a1a;
    row[96 + lane] = a1b;
    __syncthreads();

    float s_lo = 0.f, s_hi = 0.f;
#pragma unroll
    for (int ww = 0; ww < 8; ww++) {
        s_lo += sAcc[ww][t];
        s_hi += sAcc[ww][t + 256];
    }
    g_wn[(size_t)b * 512 + t]       = s_lo;
    g_wn[(size_t)b * 512 + 256 + t] = s_hi;
}

// =============================================================================
extern "C" void kernel_launch(void* const* d_in, const int* in_sizes, int n_in,
                              void* d_out, int out_size)
{
    const float* center = (const float*)d_in[0];
    const float* neigh  = (const float*)d_in[1];
    const float* wts    = (const float*)d_in[2];
    const float* Wq     = (const float*)d_in[3];
    const float* Wk     = (const float*)d_in[4];
    const float* Wv     = (const float*)d_in[5];
    const float* Wg     = (const float*)d_in[6];
    const float* bg     = (const float*)d_in[7];
    float* out = (float*)d_out;

    float *q_, *wn_, *ctx_;
    cudaGetSymbolAddress((void**)&q_,   g_q);
    cudaGetSymbolAddress((void**)&wn_,  g_wn);
    cudaGetSymbolAddress((void**)&ctx_, g_ctx);

    cudaFuncSetAttribute(gemm_dual,
                         cudaFuncAttributeMaxDynamicSharedMemorySize, GEMM_SMEM_BYTES);
    cudaFuncSetAttribute(gemm_gate,
                         cudaFuncAttributeMaxDynamicSharedMemorySize, GEMM_SMEM_BYTES);

    const dim3 blk(256);

    // q = center @ Wq^T                       [B,64]
    gemm_dual<<<dim3(256, 1), blk, GEMM_SMEM_BYTES>>>(
        center, Wq, q_, 256, 256, 64,
        center, Wq, q_, 256, 256, 64, 1);
    // p[b,h] = q[b,h] @ Wk_h                  [B,2,256]
    p_kernel<<<2048, blk>>>(Wk);
    // attention -> wn                         [B,2,256]
    attn_reg<<<NB, blk>>>(neigh, wts);
    // context_h = wn_h @ Wv_h^T               [B,256] (both heads, one launch)
    gemm_dual<<<dim3(256, 4), blk, GEMM_SMEM_BYTES>>>(
        wn_,       Wv,             ctx_,       512, 256, 256,
        wn_ + 256, Wv + 128 * 256, ctx_ + 128, 512, 256, 256, 2);
    // gate = sigmoid(concat(center,ctx) @ Wg^T + bg); out = gate*center+(1-gate)*ctx
    gemm_gate<<<dim3(256, 4), blk, GEMM_SMEM_BYTES>>>(
        center, ctx_, Wg, bg, out);
}